// round 15
// baseline (speedup 1.0000x reference)
#include <cuda_runtime.h>
#include <cuda_bf16.h>
#include <math.h>

#define NN 8192
#define DD 512
#define NC 16
#define PC 512
#define KK 256
#define SEL 4096   // NC*KK

__device__ float g_scores[NN];
__device__ int   g_selidx[SEL];
__device__ float g_selval[SEL];
__device__ int   g_pack[SEL];    // (col << 16) | outpos, ascending by col
__device__ int   g_is64;

// ---------------------------------------------------------------------------
// Detect int64 vs int32 mask layout (odd 32-bit words all zero => int64).
// ---------------------------------------------------------------------------
__global__ void detect_mask_kernel(const int* __restrict__ mask32) {
    __shared__ int ok;
    if (threadIdx.x == 0) ok = 1;
    __syncthreads();
    int bad = 0;
    for (int i = threadIdx.x; i < 4096; i += blockDim.x) {
        if (mask32[2 * i + 1] != 0) bad = 1;
    }
    if (bad) atomicExch(&ok, 0);
    __syncthreads();
    if (threadIdx.x == 0) g_is64 = ok;
}

// ---------------------------------------------------------------------------
// XLA:CPU fast exp (GenerateVF32Exp = Eigen/Cephes pexp), strict f32, unfused.
// ---------------------------------------------------------------------------
__device__ __forceinline__ float xla_expf(float x) {
    x = fminf(x,  88.3762626647950f);
    x = fmaxf(x, -88.3762626647949f);
    float fx = __fadd_rn(__fmul_rn(x, 1.44269504088896341f), 0.5f);
    fx = floorf(fx);
    float tmp = __fmul_rn(fx, 0.693359375f);
    float zz  = __fmul_rn(fx, -2.12194440e-4f);
    x = __fadd_rn(x, -tmp);
    x = __fadd_rn(x, -zz);
    float x2 = __fmul_rn(x, x);
    float y = 1.9875691500e-4f;
    y = __fadd_rn(__fmul_rn(y, x), 1.3981999507e-3f);
    y = __fadd_rn(__fmul_rn(y, x), 8.3334519073e-3f);
    y = __fadd_rn(__fmul_rn(y, x), 4.1665795894e-2f);
    y = __fadd_rn(__fmul_rn(y, x), 1.6666665459e-1f);
    y = __fadd_rn(__fmul_rn(y, x), 5.0000001201e-1f);
    y = __fadd_rn(__fmul_rn(y, x2), x);
    y = __fadd_rn(y, 1.0f);
    int n = (int)fx;
    float sc = __uint_as_float((unsigned)(n + 127) << 23);
    return __fmul_rn(y, sc);
}

// ---------------------------------------------------------------------------
// scores: per row, strictly sequential fused-FMA chain over k = 0..511.
// One thread per row, smem staging.  z = (dot+b)/100 ; s = 1/(1+exp(-z)).
// ---------------------------------------------------------------------------
__global__ void __launch_bounds__(128) scores_kernel(const float* __restrict__ X,
                                                     const float* __restrict__ W,
                                                     const float* __restrict__ b) {
    __shared__ float sW[DD];
    __shared__ float tile[128][65];
    int t = threadIdx.x;
    int row0 = blockIdx.x * 128;

    {
        float4 w4 = __ldg((const float4*)W + t);
        sW[4 * t + 0] = w4.x; sW[4 * t + 1] = w4.y;
        sW[4 * t + 2] = w4.z; sW[4 * t + 3] = w4.w;
    }

    float acc = 0.0f;
#pragma unroll 1
    for (int kt = 0; kt < 8; kt++) {
        __syncthreads();
#pragma unroll
        for (int i = 0; i < 16; i++) {
            int idx = i * 128 + t;
            int r = idx >> 4;
            int c = idx & 15;
            float4 v = __ldg((const float4*)(X + (size_t)(row0 + r) * DD + kt * 64) + c);
            tile[r][4 * c + 0] = v.x; tile[r][4 * c + 1] = v.y;
            tile[r][4 * c + 2] = v.z; tile[r][4 * c + 3] = v.w;
        }
        __syncthreads();
        const float* xr = tile[t];
        const float* wr = sW + kt * 64;
#pragma unroll
        for (int k = 0; k < 64; k++)
            acc = __fmaf_rn(xr[k], wr[k], acc);
    }

    float z = __fdiv_rn(__fadd_rn(acc, __ldg(b)), 100.0f);
    float e = xla_expf(-z);
    g_scores[row0 + t] = __fdiv_rn(1.0f, __fadd_rn(1.0f, e));
}

// ---------------------------------------------------------------------------
// Per-class selection (unchanged): stable 512-wide bitonic sort, keep 256.
// ---------------------------------------------------------------------------
__global__ void select_kernel(const int* __restrict__ mask32,
                              float* __restrict__ out_mask_part) {
    int cls = blockIdx.x;
    int t   = threadIdx.x;
    __shared__ int                s_idx[PC];
    __shared__ float              s_val[PC];
    __shared__ unsigned long long s_key[PC];
    __shared__ int                s_cnt[257];

    int stride = g_is64 ? 2 : 1;

    int base = t * 32;
    int local[32];
    int cnt = 0;
#pragma unroll 4
    for (int i = 0; i < 32; i++) {
        int pos = base + i;
        int m = __ldg(mask32 + pos * stride);
        if (m == cls) local[cnt++] = pos;
    }
    s_cnt[t] = cnt;
    __syncthreads();
    if (t == 0) {
        int acc = 0;
        for (int i = 0; i < 256; i++) { int c = s_cnt[i]; s_cnt[i] = acc; acc += c; }
        s_cnt[256] = acc;
    }
    __syncthreads();
    int off = s_cnt[t];
    for (int i = 0; i < cnt; i++) s_idx[off + i] = local[i];
    __syncthreads();

    for (int p = t; p < PC; p += 256) {
        float v = g_scores[s_idx[p]];
        s_val[p] = v;
        unsigned int fb = __float_as_uint(v);
        fb = (fb & 0x80000000u) ? ~fb : (fb | 0x80000000u);
        s_key[p] = ((unsigned long long)fb << 32) | (unsigned int)p;
    }
    __syncthreads();

    for (int k = 2; k <= PC; k <<= 1) {
        for (int j = k >> 1; j > 0; j >>= 1) {
            for (int tt = t; tt < PC; tt += 256) {
                int ixj = tt ^ j;
                if (ixj > tt) {
                    bool up = ((tt & k) == 0);
                    unsigned long long a = s_key[tt], bb = s_key[ixj];
                    if ((a > bb) == up) { s_key[tt] = bb; s_key[ixj] = a; }
                }
            }
            __syncthreads();
        }
    }

    for (int p = t; p < KK; p += 256) {
        int lp = (int)(s_key[p] & 0xffffffffu);
        int o  = cls * KK + p;
        g_selidx[o] = s_idx[lp];
        g_selval[o] = s_val[lp];
        out_mask_part[o] = (float)cls;
    }
}

// ---------------------------------------------------------------------------
// Build gather table sorted by column: g_pack[j] = (col << 16) | outpos,
// ascending col. Presence map over 8192 cols + block prefix scan. 1 block.
// ---------------------------------------------------------------------------
__global__ void __launch_bounds__(1024) colprep_kernel() {
    __shared__ int spos[NN];      // 32 KB: outpos per column, or -1
    __shared__ int scnt[1024];
    int t = threadIdx.x;
    for (int i = t; i < NN; i += 1024) spos[i] = -1;
    __syncthreads();
    for (int j = t; j < SEL; j += 1024) spos[g_selidx[j]] = j;
    __syncthreads();

    int base = t * 8;
    int cnt = 0;
#pragma unroll
    for (int i = 0; i < 8; i++) if (spos[base + i] >= 0) cnt++;
    scnt[t] = cnt;
    __syncthreads();
    // Hillis-Steele inclusive scan over 1024 counts
    for (int off = 1; off < 1024; off <<= 1) {
        int v = scnt[t];
        int add = (t >= off) ? scnt[t - off] : 0;
        __syncthreads();
        scnt[t] = v + add;
        __syncthreads();
    }
    int o = scnt[t] - cnt;   // exclusive prefix
#pragma unroll
    for (int i = 0; i < 8; i++) {
        int p = spos[base + i];
        if (p >= 0) g_pack[o++] = ((base + i) << 16) | p;
    }
}

// ---------------------------------------------------------------------------
// X_out[r, :] = X[idx[r], :] * val[r]
// ---------------------------------------------------------------------------
__global__ void xout_kernel(const float* __restrict__ X, float* __restrict__ outX) {
    int r   = blockIdx.x;
    int src = g_selidx[r];
    float v = g_selval[r];
    const float4* xs = (const float4*)(X + (size_t)src * DD);
    float4*       xd = (float4*)(outX + (size_t)r * DD);
    int c = threadIdx.x;
    float4 a = __ldg(xs + c);
    a.x = __fmul_rn(a.x, v); a.y = __fmul_rn(a.y, v);
    a.z = __fmul_rn(a.z, v); a.w = __fmul_rn(a.w, v);
    xd[c] = a;
}

// ---------------------------------------------------------------------------
// M_out[r, c] = M[idx[r], idx[c]]   grid=4096 rows, block=512.
// Gather in ASCENDING column order (near-streaming reads, ~4 hits / 32B
// sector), scatter into smem output row, write back coalesced float4.
// ---------------------------------------------------------------------------
__global__ void __launch_bounds__(512) mout_kernel(const float* __restrict__ M,
                                                   float* __restrict__ outM) {
    __shared__ int   pack[SEL];    // 16 KB
    __shared__ float orow[SEL];    // 16 KB
    int t = threadIdx.x;
    for (int i = t; i < SEL; i += 512) pack[i] = g_pack[i];
    __syncthreads();

    int r = blockIdx.x;
    const float* src = M + (size_t)g_selidx[r] * NN;
#pragma unroll 8
    for (int c = t; c < SEL; c += 512) {
        int e = pack[c];
        orow[e & 0xffff] = __ldg(src + (e >> 16));
    }
    __syncthreads();

    float4*       dst = (float4*)(outM + (size_t)r * SEL);
    const float4* so  = (const float4*)orow;
#pragma unroll 2
    for (int i = t; i < SEL / 4; i += 512) dst[i] = so[i];
}

// ---------------------------------------------------------------------------
extern "C" void kernel_launch(void* const* d_in, const int* in_sizes, int n_in,
                              void* d_out, int out_size) {
    const float* M    = (const float*)d_in[0];
    const float* X    = (const float*)d_in[1];
    const int*   mask = (const int*)d_in[2];
    const float* W    = (const float*)d_in[3];
    const float* b    = (const float*)d_in[4];

    float* out   = (float*)d_out;
    float* outM  = out;                                  // 4096*4096
    float* outX  = out + (size_t)SEL * SEL;              // 4096*512
    float* outMk = outX + (size_t)SEL * DD;              // 4096

    detect_mask_kernel<<<1, 256>>>(mask);
    scores_kernel<<<NN / 128, 128>>>(X, W, b);
    select_kernel<<<NC, 256>>>(mask, outMk);
    colprep_kernel<<<1, 1024>>>();
    xout_kernel<<<SEL, 128>>>(X, outX);
    mout_kernel<<<SEL, 512>>>(M, outM);
}

// round 16
// speedup vs baseline: 1.3199x; 1.3199x over previous
#include <cuda_runtime.h>
#include <cuda_bf16.h>
#include <math.h>

#define NN 8192
#define DD 512
#define NC 16
#define PC 512
#define KK 256
#define SEL 4096   // NC*KK

__device__ float g_scores[NN];
__device__ int   g_selidx[SEL];
__device__ float g_selval[SEL];
__device__ int   g_is64;

// ---------------------------------------------------------------------------
// Detect int64 vs int32 mask layout (odd 32-bit words all zero => int64).
// ---------------------------------------------------------------------------
__global__ void detect_mask_kernel(const int* __restrict__ mask32) {
    __shared__ int ok;
    if (threadIdx.x == 0) ok = 1;
    __syncthreads();
    int bad = 0;
    for (int i = threadIdx.x; i < 4096; i += blockDim.x) {
        if (mask32[2 * i + 1] != 0) bad = 1;
    }
    if (bad) atomicExch(&ok, 0);
    __syncthreads();
    if (threadIdx.x == 0) g_is64 = ok;
}

// ---------------------------------------------------------------------------
// XLA:CPU fast exp (GenerateVF32Exp = Eigen/Cephes pexp), strict f32, unfused.
// ---------------------------------------------------------------------------
__device__ __forceinline__ float xla_expf(float x) {
    x = fminf(x,  88.3762626647950f);
    x = fmaxf(x, -88.3762626647949f);
    float fx = __fadd_rn(__fmul_rn(x, 1.44269504088896341f), 0.5f);
    fx = floorf(fx);
    float tmp = __fmul_rn(fx, 0.693359375f);
    float zz  = __fmul_rn(fx, -2.12194440e-4f);
    x = __fadd_rn(x, -tmp);
    x = __fadd_rn(x, -zz);
    float x2 = __fmul_rn(x, x);
    float y = 1.9875691500e-4f;
    y = __fadd_rn(__fmul_rn(y, x), 1.3981999507e-3f);
    y = __fadd_rn(__fmul_rn(y, x), 8.3334519073e-3f);
    y = __fadd_rn(__fmul_rn(y, x), 4.1665795894e-2f);
    y = __fadd_rn(__fmul_rn(y, x), 1.6666665459e-1f);
    y = __fadd_rn(__fmul_rn(y, x), 5.0000001201e-1f);
    y = __fadd_rn(__fmul_rn(y, x2), x);
    y = __fadd_rn(y, 1.0f);
    int n = (int)fx;
    float sc = __uint_as_float((unsigned)(n + 127) << 23);
    return __fmul_rn(y, sc);
}

// ---------------------------------------------------------------------------
// scores: per row, strictly sequential fused-FMA chain over k = 0..511.
// One thread per row, smem staging.  z = (dot+b)/100 ; s = 1/(1+exp(-z)).
// ---------------------------------------------------------------------------
__global__ void __launch_bounds__(128) scores_kernel(const float* __restrict__ X,
                                                     const float* __restrict__ W,
                                                     const float* __restrict__ b) {
    __shared__ float sW[DD];
    __shared__ float tile[128][65];
    int t = threadIdx.x;
    int row0 = blockIdx.x * 128;

    {
        float4 w4 = __ldg((const float4*)W + t);
        sW[4 * t + 0] = w4.x; sW[4 * t + 1] = w4.y;
        sW[4 * t + 2] = w4.z; sW[4 * t + 3] = w4.w;
    }

    float acc = 0.0f;
#pragma unroll 1
    for (int kt = 0; kt < 8; kt++) {
        __syncthreads();
#pragma unroll
        for (int i = 0; i < 16; i++) {
            int idx = i * 128 + t;
            int r = idx >> 4;
            int c = idx & 15;
            float4 v = __ldg((const float4*)(X + (size_t)(row0 + r) * DD + kt * 64) + c);
            tile[r][4 * c + 0] = v.x; tile[r][4 * c + 1] = v.y;
            tile[r][4 * c + 2] = v.z; tile[r][4 * c + 3] = v.w;
        }
        __syncthreads();
        const float* xr = tile[t];
        const float* wr = sW + kt * 64;
#pragma unroll
        for (int k = 0; k < 64; k++)
            acc = __fmaf_rn(xr[k], wr[k], acc);
    }

    float z = __fdiv_rn(__fadd_rn(acc, __ldg(b)), 100.0f);
    float e = xla_expf(-z);
    g_scores[row0 + t] = __fdiv_rn(1.0f, __fadd_rn(1.0f, e));
}

// ---------------------------------------------------------------------------
// Per-class selection: stable 512-wide bitonic sort, keep smallest 256.
// ---------------------------------------------------------------------------
__global__ void select_kernel(const int* __restrict__ mask32,
                              float* __restrict__ out_mask_part) {
    int cls = blockIdx.x;
    int t   = threadIdx.x;
    __shared__ int                s_idx[PC];
    __shared__ float              s_val[PC];
    __shared__ unsigned long long s_key[PC];
    __shared__ int                s_cnt[257];

    int stride = g_is64 ? 2 : 1;

    int base = t * 32;
    int local[32];
    int cnt = 0;
#pragma unroll 4
    for (int i = 0; i < 32; i++) {
        int pos = base + i;
        int m = __ldg(mask32 + pos * stride);
        if (m == cls) local[cnt++] = pos;
    }
    s_cnt[t] = cnt;
    __syncthreads();
    if (t == 0) {
        int acc = 0;
        for (int i = 0; i < 256; i++) { int c = s_cnt[i]; s_cnt[i] = acc; acc += c; }
        s_cnt[256] = acc;
    }
    __syncthreads();
    int off = s_cnt[t];
    for (int i = 0; i < cnt; i++) s_idx[off + i] = local[i];
    __syncthreads();

    for (int p = t; p < PC; p += 256) {
        float v = g_scores[s_idx[p]];
        s_val[p] = v;
        unsigned int fb = __float_as_uint(v);
        fb = (fb & 0x80000000u) ? ~fb : (fb | 0x80000000u);
        s_key[p] = ((unsigned long long)fb << 32) | (unsigned int)p;
    }
    __syncthreads();

    for (int k = 2; k <= PC; k <<= 1) {
        for (int j = k >> 1; j > 0; j >>= 1) {
            for (int tt = t; tt < PC; tt += 256) {
                int ixj = tt ^ j;
                if (ixj > tt) {
                    bool up = ((tt & k) == 0);
                    unsigned long long a = s_key[tt], bb = s_key[ixj];
                    if ((a > bb) == up) { s_key[tt] = bb; s_key[ixj] = a; }
                }
            }
            __syncthreads();
        }
    }

    for (int p = t; p < KK; p += 256) {
        int lp = (int)(s_key[p] & 0xffffffffu);
        int o  = cls * KK + p;
        g_selidx[o] = s_idx[lp];
        g_selval[o] = s_val[lp];
        out_mask_part[o] = (float)cls;
    }
}

// ---------------------------------------------------------------------------
// X_out[r, :] = X[idx[r], :] * val[r]
// ---------------------------------------------------------------------------
__global__ void xout_kernel(const float* __restrict__ X, float* __restrict__ outX) {
    int r   = blockIdx.x;
    int src = g_selidx[r];
    float v = g_selval[r];
    const float4* xs = (const float4*)(X + (size_t)src * DD);
    float4*       xd = (float4*)(outX + (size_t)r * DD);
    int c = threadIdx.x;
    float4 a = __ldg(xs + c);
    a.x = __fmul_rn(a.x, v); a.y = __fmul_rn(a.y, v);
    a.z = __fmul_rn(a.z, v); a.w = __fmul_rn(a.w, v);
    xd[c] = a;
}

// ---------------------------------------------------------------------------
// M_out[r, c] = M[idx[r], idx[c]]   grid=4096 rows, block=512.
// Density 0.5 => the scattered gather touches ~every 32B sector of the 32KB
// source row anyway. So: stream the FULL row coalesced into smem (float4),
// gather from smem (bank-random, cheap), write coalesced float4.
// Pure streaming: 128MB read + 64MB write at LTS cap.
// ---------------------------------------------------------------------------
__global__ void __launch_bounds__(512) mout_kernel(const float* __restrict__ M,
                                                   float* __restrict__ outM) {
    __shared__ float row[NN];      // 32 KB
    int t = threadIdx.x;
    int r = blockIdx.x;

    const float4* src = (const float4*)(M + (size_t)g_selidx[r] * NN);
    float4* srow = (float4*)row;
#pragma unroll
    for (int i = 0; i < 4; i++)
        srow[t + i * 512] = __ldg(src + t + i * 512);
    __syncthreads();

    const int4* idx4 = (const int4*)g_selidx;      // L1/L2-cached, coalesced
    float4*     dst  = (float4*)(outM + (size_t)r * SEL);
#pragma unroll
    for (int i = 0; i < 2; i++) {
        int4 c4 = __ldg(idx4 + t + i * 512);
        float4 v;
        v.x = row[c4.x]; v.y = row[c4.y];
        v.z = row[c4.z]; v.w = row[c4.w];
        dst[t + i * 512] = v;
    }
}

// ---------------------------------------------------------------------------
extern "C" void kernel_launch(void* const* d_in, const int* in_sizes, int n_in,
                              void* d_out, int out_size) {
    const float* M    = (const float*)d_in[0];
    const float* X    = (const float*)d_in[1];
    const int*   mask = (const int*)d_in[2];
    const float* W    = (const float*)d_in[3];
    const float* b    = (const float*)d_in[4];

    float* out   = (float*)d_out;
    float* outM  = out;                                  // 4096*4096
    float* outX  = out + (size_t)SEL * SEL;              // 4096*512
    float* outMk = outX + (size_t)SEL * DD;              // 4096

    detect_mask_kernel<<<1, 256>>>(mask);
    scores_kernel<<<NN / 128, 128>>>(X, W, b);
    select_kernel<<<NC, 256>>>(mask, outMk);
    xout_kernel<<<SEL, 128>>>(X, outX);
    mout_kernel<<<SEL, 512>>>(M, outM);
}